// round 2
// baseline (speedup 1.0000x reference)
#include <cuda_runtime.h>
#include <cstdint>
#include <cstddef>

// Problem dims
#define B_    64
#define S_    1024
#define I_    512
#define H_    512
#define G4H   2048
#define M_TOT (B_ * S_)        // 65536

typedef unsigned long long u64;

// ---------------- device scratch (no allocations allowed) ----------------
__device__ float    g_xproj[(size_t)S_ * B_ * G4H];   // 512 MB, layout (S, B, 4H)
__device__ float    g_hbuf[2][B_ * H_];               // ping-pong h
__device__ float    g_bias[G4H];
__device__ unsigned g_count;                          // grid barrier counter

// ---------------- f32x2 helpers (Blackwell packed fp32) ----------------
__device__ __forceinline__ u64 pk2(float x, float y) {
    u64 r; asm("mov.b64 %0,{%1,%2};" : "=l"(r) : "f"(x), "f"(y)); return r;
}
__device__ __forceinline__ void upk2(u64 p, float& x, float& y) {
    asm("mov.b64 {%0,%1},%2;" : "=f"(x), "=f"(y) : "l"(p));
}
__device__ __forceinline__ void ffma2(u64& d, u64 a, u64 b) {
    asm("fma.rn.f32x2 %0,%1,%2,%0;" : "+l"(d) : "l"(a), "l"(b));
}

// fast transcendentals (~1e-7 rel err: ex2.approx + rcp.approx)
__device__ __forceinline__ float fexp_(float x) {
    float r; asm("ex2.approx.f32 %0,%1;" : "=f"(r) : "f"(x * 1.4426950408889634f)); return r;
}
__device__ __forceinline__ float frcp_(float x) {
    float r; asm("rcp.approx.f32 %0,%1;" : "=f"(r) : "f"(x)); return r;
}
__device__ __forceinline__ float fsig_(float x)  { return frcp_(1.0f + fexp_(-x)); }
__device__ __forceinline__ float ftanh_(float x) { return 1.0f - 2.0f * frcp_(1.0f + fexp_(2.0f * x)); }

// =====================================================================
// prep: combined bias + barrier counter reset
// =====================================================================
__global__ void prep_kernel(const float* __restrict__ b_ii, const float* __restrict__ b_if,
                            const float* __restrict__ b_ig, const float* __restrict__ b_io,
                            const float* __restrict__ b_hi, const float* __restrict__ b_hf,
                            const float* __restrict__ b_hg, const float* __restrict__ b_ho)
{
    int gidx = blockIdx.x * blockDim.x + threadIdx.x;
    if (gidx == 0) g_count = 0u;
    if (gidx < G4H) {
        int j   = gidx & (H_ - 1);
        int sel = gidx >> 9;
        float v;
        if      (sel == 0) v = b_ii[j] + b_hi[j];
        else if (sel == 1) v = b_if[j] + b_hf[j];
        else if (sel == 2) v = b_ig[j] + b_hg[j];
        else               v = b_io[j] + b_ho[j];
        g_bias[gidx] = v;
    }
}

// =====================================================================
// x_proj GEMM with f32x2 inner loop.
// =====================================================================
#define GM 128
#define GN 128
#define GK 16

__global__ __launch_bounds__(256, 2)
void xproj_gemm(const float* __restrict__ A,
                const float* __restrict__ w_ii, const float* __restrict__ w_if,
                const float* __restrict__ w_ig, const float* __restrict__ w_io)
{
    __shared__ float sA[GK][GM + 4];
    __shared__ float sB[GK][GN + 4];

    const int tid   = threadIdx.x;
    const int mBase = blockIdx.y * GM;
    const int nBase = blockIdx.x * GN;
    const float* W = (nBase < 512) ? w_ii : (nBase < 1024) ? w_if : (nBase < 1536) ? w_ig : w_io;
    const int jBase = nBase & (H_ - 1);

    const int lrow = tid >> 1;
    const int lk   = (tid & 1) << 3;
    const float* Ar = A + (size_t)(mBase + lrow) * I_ + lk;
    const float* Br = W + (size_t)(jBase + lrow) * I_ + lk;

    const int tx = tid & 15;
    const int ty = tid >> 4;

    u64 acc2[8][4];
#pragma unroll
    for (int i = 0; i < 8; i++)
#pragma unroll
        for (int j = 0; j < 4; j++) acc2[i][j] = 0ull;

    float4 a0 = *(const float4*)(Ar);
    float4 a1 = *(const float4*)(Ar + 4);
    float4 b0 = *(const float4*)(Br);
    float4 b1 = *(const float4*)(Br + 4);

    for (int k0 = 0; k0 < I_; k0 += GK) {
        sA[lk + 0][lrow] = a0.x; sA[lk + 1][lrow] = a0.y;
        sA[lk + 2][lrow] = a0.z; sA[lk + 3][lrow] = a0.w;
        sA[lk + 4][lrow] = a1.x; sA[lk + 5][lrow] = a1.y;
        sA[lk + 6][lrow] = a1.z; sA[lk + 7][lrow] = a1.w;
        sB[lk + 0][lrow] = b0.x; sB[lk + 1][lrow] = b0.y;
        sB[lk + 2][lrow] = b0.z; sB[lk + 3][lrow] = b0.w;
        sB[lk + 4][lrow] = b1.x; sB[lk + 5][lrow] = b1.y;
        sB[lk + 6][lrow] = b1.z; sB[lk + 7][lrow] = b1.w;
        __syncthreads();

        if (k0 + GK < I_) {
            a0 = *(const float4*)(Ar + k0 + GK);
            a1 = *(const float4*)(Ar + k0 + GK + 4);
            b0 = *(const float4*)(Br + k0 + GK);
            b1 = *(const float4*)(Br + k0 + GK + 4);
        }

#pragma unroll
        for (int kk = 0; kk < GK; kk++) {
            float ar[8];
            *(float4*)(ar)     = *(const float4*)(&sA[kk][ty * 4]);
            *(float4*)(ar + 4) = *(const float4*)(&sA[kk][64 + ty * 4]);
            ulonglong2 bq0 = *(const ulonglong2*)(&sB[kk][tx * 4]);       // n pairs (0,1),(2,3)
            ulonglong2 bq1 = *(const ulonglong2*)(&sB[kk][64 + tx * 4]);
#pragma unroll
            for (int i = 0; i < 8; i++) {
                u64 ad = pk2(ar[i], ar[i]);
                ffma2(acc2[i][0], ad, bq0.x);
                ffma2(acc2[i][1], ad, bq0.y);
                ffma2(acc2[i][2], ad, bq1.x);
                ffma2(acc2[i][3], ad, bq1.y);
            }
        }
        __syncthreads();
    }

    float4 bias0 = *(const float4*)(g_bias + nBase + tx * 4);
    float4 bias1 = *(const float4*)(g_bias + nBase + 64 + tx * 4);
#pragma unroll
    for (int i = 0; i < 8; i++) {
        int ml = (i < 4) ? (ty * 4 + i) : (64 + ty * 4 + (i - 4));
        int m  = mBase + ml;
        int b  = m >> 10;
        int t  = m & (S_ - 1);
        float* dst = g_xproj + ((size_t)t * B_ + b) * G4H + nBase;
        float4 v0, v1;
        upk2(acc2[i][0], v0.x, v0.y);
        upk2(acc2[i][1], v0.z, v0.w);
        upk2(acc2[i][2], v1.x, v1.y);
        upk2(acc2[i][3], v1.z, v1.w);
        v0.x += bias0.x; v0.y += bias0.y; v0.z += bias0.z; v0.w += bias0.w;
        v1.x += bias1.x; v1.y += bias1.y; v1.z += bias1.z; v1.w += bias1.w;
        *(float4*)(dst + tx * 4)      = v0;
        *(float4*)(dst + 64 + tx * 4) = v1;
    }
}

// =====================================================================
// Persistent LSTM scan v2: weights in registers, f32x2 FMA.
// 128 CTAs x 128 threads. CTA owns hidden units j0..j0+3.
// Warp w = gate w. Lane (rg = lane>>3, kg = lane&7):
//   holds W[gate w][unit j0+rg][k = kg*64 .. kg*64+63] in 32 u64 regs.
// h staged to smem each step; dot reads swizzled ((i+kg)&15) -> conflict-free.
// Cross-kg reduction: 3-round shfl_xor. c state in registers (2 cells/thread).
// =====================================================================
#define SCAN_CTAS    128
#define SCAN_THREADS 128
#define SH_FLOATS    (B_ * H_)           // 32768 floats = 128 KB
#define SG_STRIDE    17
#define SG_FLOATS    (B_ * SG_STRIDE)
#define SMEM_BYTES   ((SH_FLOATS + SG_FLOATS) * 4)

__global__ __launch_bounds__(SCAN_THREADS, 1)
void lstm_scan(const float* __restrict__ h0, const float* __restrict__ c0,
               const float* __restrict__ w_hi, const float* __restrict__ w_hf,
               const float* __restrict__ w_hg, const float* __restrict__ w_ho,
               float* __restrict__ out)
{
    extern __shared__ float sm[];
    float* sH = sm;                   // [64][512]
    float* sG = sm + SH_FLOATS;       // [64][17] (16 gate rows + pad)

    const int tid  = threadIdx.x;
    const int w    = tid >> 5;        // warp index == gate index (i,f,g,o)
    const int lane = tid & 31;
    const int rg   = lane >> 3;       // local unit 0..3
    const int kg   = lane & 7;        // k-chunk 0..7 (64 k each)
    const int cta  = blockIdx.x;
    const int j0   = cta * 4;

    // ---- load this lane's weight slice into registers (stays for whole scan)
    const float* wptr = (w == 0) ? w_hi : (w == 1) ? w_hf : (w == 2) ? w_hg : w_ho;
    const u64* ws = (const u64*)(wptr + (size_t)(j0 + rg) * H_ + kg * 64);
    u64 wreg[32];
#pragma unroll
    for (int p = 0; p < 32; p++) wreg[p] = ws[p];

    // elementwise cell mapping: cells tid and tid+128 (b = c>>2, jl = c&3)
    const int b0c = tid >> 2;
    const int b1c = (tid + 128) >> 2;
    const int jl  = tid & 3;
    float creg0 = c0[b0c * H_ + j0 + jl];
    float creg1 = c0[b1c * H_ + j0 + jl];

    const int sgrow = w * 4 + rg;
    const size_t OFS = (size_t)B_ * S_ * H_;

    for (int t = 0; t < S_; t++) {
        const float4* hsrc = (t == 0) ? (const float4*)h0
                                      : (const float4*)g_hbuf[(t - 1) & 1];
        // prefetch x_proj (independent of h; hides DRAM latency behind staging+dot)
        const float* xr0 = g_xproj + ((size_t)t * B_ + b0c) * G4H + (j0 + jl);
        const float* xr1 = g_xproj + ((size_t)t * B_ + b1c) * G4H + (j0 + jl);
        float xi0 = xr0[0], xf0 = xr0[512], xg0 = xr0[1024], xo0 = xr0[1536];
        float xi1 = xr1[0], xf1 = xr1[512], xg1 = xr1[1024], xo1 = xr1[1536];

        // ---- stage h(t-1) into shared (L2-coherent reads)
#pragma unroll 8
        for (int i = 0; i < 64; i++) {
            int idx = tid + i * SCAN_THREADS;   // 0..8191 float4
            ((float4*)sH)[idx] = __ldcg(&hsrc[idx]);
        }
        __syncthreads();

        // ---- dot phase: 2 batches per iteration, 4 f32x2 accumulator chains
        for (int b = 0; b < B_; b += 2) {
            const ulonglong2* p0 = (const ulonglong2*)(sH + (b    ) * H_ + kg * 64);
            const ulonglong2* p1 = (const ulonglong2*)(sH + (b + 1) * H_ + kg * 64);
            u64 a0 = 0ull, a1 = 0ull, a2 = 0ull, a3 = 0ull;
#pragma unroll
            for (int i = 0; i < 16; i += 2) {
                int ia = (i + kg) & 15;
                int ib = (i + 1 + kg) & 15;
                ulonglong2 h0v = p0[ia];
                ulonglong2 h1v = p1[ia];
                ffma2(a0, h0v.x, wreg[2 * ia]); ffma2(a0, h0v.y, wreg[2 * ia + 1]);
                ffma2(a2, h1v.x, wreg[2 * ia]); ffma2(a2, h1v.y, wreg[2 * ia + 1]);
                ulonglong2 h0w = p0[ib];
                ulonglong2 h1w = p1[ib];
                ffma2(a1, h0w.x, wreg[2 * ib]); ffma2(a1, h0w.y, wreg[2 * ib + 1]);
                ffma2(a3, h1w.x, wreg[2 * ib]); ffma2(a3, h1w.y, wreg[2 * ib + 1]);
            }
            float x, y, s0, s1;
            upk2(a0, x, y); s0 = x + y;
            upk2(a1, x, y); s0 += x + y;
            upk2(a2, x, y); s1 = x + y;
            upk2(a3, x, y); s1 += x + y;
            s0 += __shfl_xor_sync(0xffffffffu, s0, 1);
            s0 += __shfl_xor_sync(0xffffffffu, s0, 2);
            s0 += __shfl_xor_sync(0xffffffffu, s0, 4);
            s1 += __shfl_xor_sync(0xffffffffu, s1, 1);
            s1 += __shfl_xor_sync(0xffffffffu, s1, 2);
            s1 += __shfl_xor_sync(0xffffffffu, s1, 4);
            if (kg == 0) {
                sG[b * SG_STRIDE + sgrow]       = s0;
                sG[(b + 1) * SG_STRIDE + sgrow] = s1;
            }
        }
        __syncthreads();

        // ---- elementwise LSTM cell update (2 cells per thread)
        {
            float gi = sG[b0c * SG_STRIDE + jl]      + xi0;
            float gf = sG[b0c * SG_STRIDE + 4 + jl]  + xf0;
            float gg = sG[b0c * SG_STRIDE + 8 + jl]  + xg0;
            float go = sG[b0c * SG_STRIDE + 12 + jl] + xo0;
            float it = fsig_(gi), ft = fsig_(gf), gt = ftanh_(gg), ot = fsig_(go);
            creg0 = ft * creg0 + it * gt;
            float hv = ot * ftanh_(creg0);
            g_hbuf[t & 1][b0c * H_ + j0 + jl] = hv;
            out[((size_t)b0c * S_ + t) * H_ + j0 + jl] = hv;
            if (t == S_ - 1) {
                out[OFS + b0c * H_ + j0 + jl]           = hv;
                out[OFS + B_ * H_ + b0c * H_ + j0 + jl] = creg0;
            }
        }
        {
            float gi = sG[b1c * SG_STRIDE + jl]      + xi1;
            float gf = sG[b1c * SG_STRIDE + 4 + jl]  + xf1;
            float gg = sG[b1c * SG_STRIDE + 8 + jl]  + xg1;
            float go = sG[b1c * SG_STRIDE + 12 + jl] + xo1;
            float it = fsig_(gi), ft = fsig_(gf), gt = ftanh_(gg), ot = fsig_(go);
            creg1 = ft * creg1 + it * gt;
            float hv = ot * ftanh_(creg1);
            g_hbuf[t & 1][b1c * H_ + j0 + jl] = hv;
            out[((size_t)b1c * S_ + t) * H_ + j0 + jl] = hv;
            if (t == S_ - 1) {
                out[OFS + b1c * H_ + j0 + jl]           = hv;
                out[OFS + B_ * H_ + b1c * H_ + j0 + jl] = creg1;
            }
        }

        // ---- grid barrier
        __syncthreads();
        if (tid == 0) {
            __threadfence();
            atomicAdd(&g_count, 1u);
            unsigned target = (unsigned)(t + 1) * (unsigned)SCAN_CTAS;
            while (*(volatile unsigned*)&g_count < target) { }
            __threadfence();
        }
        __syncthreads();
    }
}

// =====================================================================
extern "C" void kernel_launch(void* const* d_in, const int* in_sizes, int n_in,
                              void* d_out, int out_size)
{
    const float* inputs = (const float*)d_in[0];
    const float* h0     = (const float*)d_in[1];
    const float* c0     = (const float*)d_in[2];
    const float* w_ii   = (const float*)d_in[3];
    const float* w_if   = (const float*)d_in[4];
    const float* w_ig   = (const float*)d_in[5];
    const float* w_io   = (const float*)d_in[6];
    const float* w_hi   = (const float*)d_in[7];
    const float* w_hf   = (const float*)d_in[8];
    const float* w_hg   = (const float*)d_in[9];
    const float* w_ho   = (const float*)d_in[10];
    const float* b_ii   = (const float*)d_in[11];
    const float* b_if   = (const float*)d_in[12];
    const float* b_ig   = (const float*)d_in[13];
    const float* b_io   = (const float*)d_in[14];
    const float* b_hi   = (const float*)d_in[15];
    const float* b_hf   = (const float*)d_in[16];
    const float* b_ho   = (const float*)d_in[17];  // dict order: b_ho before b_hg
    const float* b_hg   = (const float*)d_in[18];
    float* out = (float*)d_out;

    cudaFuncSetAttribute(lstm_scan, cudaFuncAttributeMaxDynamicSharedMemorySize, SMEM_BYTES);

    prep_kernel<<<4, 512>>>(b_ii, b_if, b_ig, b_io, b_hi, b_hf, b_hg, b_ho);
    xproj_gemm<<<dim3(G4H / GN, M_TOT / GM), 256>>>(inputs, w_ii, w_if, w_ig, w_io);
    lstm_scan<<<SCAN_CTAS, SCAN_THREADS, SMEM_BYTES>>>(h0, c0, w_hi, w_hf, w_hg, w_ho, out);
}

// round 3
// speedup vs baseline: 1.0001x; 1.0001x over previous
#include <cuda_runtime.h>
#include <cstdint>
#include <cstddef>

// Problem dims
#define B_    64
#define S_    1024
#define I_    512
#define H_    512
#define G4H   2048
#define M_TOT (B_ * S_)        // 65536

typedef unsigned long long u64;

// ---------------- device scratch (no allocations allowed) ----------------
__device__ float    g_xproj[(size_t)S_ * B_ * G4H];   // 512 MB, layout (S, B, 4H)
__device__ float    g_hbuf[2][B_ * H_];               // ping-pong h
__device__ float    g_bias[G4H];
__device__ unsigned g_count;                          // grid barrier counter

// ---------------- f32x2 helpers (Blackwell packed fp32) ----------------
__device__ __forceinline__ u64 pk2(float x, float y) {
    u64 r; asm("mov.b64 %0,{%1,%2};" : "=l"(r) : "f"(x), "f"(y)); return r;
}
__device__ __forceinline__ void upk2(u64 p, float& x, float& y) {
    asm("mov.b64 {%0,%1},%2;" : "=f"(x), "=f"(y) : "l"(p));
}
__device__ __forceinline__ void ffma2(u64& d, u64 a, u64 b) {
    asm("fma.rn.f32x2 %0,%1,%2,%0;" : "+l"(d) : "l"(a), "l"(b));
}

// fast transcendentals (~1e-7 rel err: ex2.approx + rcp.approx)
__device__ __forceinline__ float fexp_(float x) {
    float r; asm("ex2.approx.f32 %0,%1;" : "=f"(r) : "f"(x * 1.4426950408889634f)); return r;
}
__device__ __forceinline__ float frcp_(float x) {
    float r; asm("rcp.approx.f32 %0,%1;" : "=f"(r) : "f"(x)); return r;
}
__device__ __forceinline__ float fsig_(float x)  { return frcp_(1.0f + fexp_(-x)); }
__device__ __forceinline__ float ftanh_(float x) { return 1.0f - 2.0f * frcp_(1.0f + fexp_(2.0f * x)); }

// =====================================================================
// prep: combined bias + barrier counter reset
// =====================================================================
__global__ void prep_kernel(const float* __restrict__ b_ii, const float* __restrict__ b_if,
                            const float* __restrict__ b_ig, const float* __restrict__ b_io,
                            const float* __restrict__ b_hi, const float* __restrict__ b_hf,
                            const float* __restrict__ b_hg, const float* __restrict__ b_ho)
{
    int gidx = blockIdx.x * blockDim.x + threadIdx.x;
    if (gidx == 0) g_count = 0u;
    if (gidx < G4H) {
        int j   = gidx & (H_ - 1);
        int sel = gidx >> 9;
        float v;
        if      (sel == 0) v = b_ii[j] + b_hi[j];
        else if (sel == 1) v = b_if[j] + b_hf[j];
        else if (sel == 2) v = b_ig[j] + b_hg[j];
        else               v = b_io[j] + b_ho[j];
        g_bias[gidx] = v;
    }
}

// =====================================================================
// x_proj GEMM with f32x2 inner loop.
// =====================================================================
#define GM 128
#define GN 128
#define GK 16

__global__ __launch_bounds__(256, 2)
void xproj_gemm(const float* __restrict__ A,
                const float* __restrict__ w_ii, const float* __restrict__ w_if,
                const float* __restrict__ w_ig, const float* __restrict__ w_io)
{
    __shared__ float sA[GK][GM + 4];
    __shared__ float sB[GK][GN + 4];

    const int tid   = threadIdx.x;
    const int mBase = blockIdx.y * GM;
    const int nBase = blockIdx.x * GN;
    const float* W = (nBase < 512) ? w_ii : (nBase < 1024) ? w_if : (nBase < 1536) ? w_ig : w_io;
    const int jBase = nBase & (H_ - 1);

    const int lrow = tid >> 1;
    const int lk   = (tid & 1) << 3;
    const float* Ar = A + (size_t)(mBase + lrow) * I_ + lk;
    const float* Br = W + (size_t)(jBase + lrow) * I_ + lk;

    const int tx = tid & 15;
    const int ty = tid >> 4;

    u64 acc2[8][4];
#pragma unroll
    for (int i = 0; i < 8; i++)
#pragma unroll
        for (int j = 0; j < 4; j++) acc2[i][j] = 0ull;

    float4 a0 = *(const float4*)(Ar);
    float4 a1 = *(const float4*)(Ar + 4);
    float4 b0 = *(const float4*)(Br);
    float4 b1 = *(const float4*)(Br + 4);

    for (int k0 = 0; k0 < I_; k0 += GK) {
        sA[lk + 0][lrow] = a0.x; sA[lk + 1][lrow] = a0.y;
        sA[lk + 2][lrow] = a0.z; sA[lk + 3][lrow] = a0.w;
        sA[lk + 4][lrow] = a1.x; sA[lk + 5][lrow] = a1.y;
        sA[lk + 6][lrow] = a1.z; sA[lk + 7][lrow] = a1.w;
        sB[lk + 0][lrow] = b0.x; sB[lk + 1][lrow] = b0.y;
        sB[lk + 2][lrow] = b0.z; sB[lk + 3][lrow] = b0.w;
        sB[lk + 4][lrow] = b1.x; sB[lk + 5][lrow] = b1.y;
        sB[lk + 6][lrow] = b1.z; sB[lk + 7][lrow] = b1.w;
        __syncthreads();

        if (k0 + GK < I_) {
            a0 = *(const float4*)(Ar + k0 + GK);
            a1 = *(const float4*)(Ar + k0 + GK + 4);
            b0 = *(const float4*)(Br + k0 + GK);
            b1 = *(const float4*)(Br + k0 + GK + 4);
        }

#pragma unroll
        for (int kk = 0; kk < GK; kk++) {
            float ar[8];
            *(float4*)(ar)     = *(const float4*)(&sA[kk][ty * 4]);
            *(float4*)(ar + 4) = *(const float4*)(&sA[kk][64 + ty * 4]);
            ulonglong2 bq0 = *(const ulonglong2*)(&sB[kk][tx * 4]);       // n pairs (0,1),(2,3)
            ulonglong2 bq1 = *(const ulonglong2*)(&sB[kk][64 + tx * 4]);
#pragma unroll
            for (int i = 0; i < 8; i++) {
                u64 ad = pk2(ar[i], ar[i]);
                ffma2(acc2[i][0], ad, bq0.x);
                ffma2(acc2[i][1], ad, bq0.y);
                ffma2(acc2[i][2], ad, bq1.x);
                ffma2(acc2[i][3], ad, bq1.y);
            }
        }
        __syncthreads();
    }

    float4 bias0 = *(const float4*)(g_bias + nBase + tx * 4);
    float4 bias1 = *(const float4*)(g_bias + nBase + 64 + tx * 4);
#pragma unroll
    for (int i = 0; i < 8; i++) {
        int ml = (i < 4) ? (ty * 4 + i) : (64 + ty * 4 + (i - 4));
        int m  = mBase + ml;
        int b  = m >> 10;
        int t  = m & (S_ - 1);
        float* dst = g_xproj + ((size_t)t * B_ + b) * G4H + nBase;
        float4 v0, v1;
        upk2(acc2[i][0], v0.x, v0.y);
        upk2(acc2[i][1], v0.z, v0.w);
        upk2(acc2[i][2], v1.x, v1.y);
        upk2(acc2[i][3], v1.z, v1.w);
        v0.x += bias0.x; v0.y += bias0.y; v0.z += bias0.z; v0.w += bias0.w;
        v1.x += bias1.x; v1.y += bias1.y; v1.z += bias1.z; v1.w += bias1.w;
        *(float4*)(dst + tx * 4)      = v0;
        *(float4*)(dst + 64 + tx * 4) = v1;
    }
}

// =====================================================================
// Persistent LSTM scan v2: weights in registers, f32x2 FMA.
// 128 CTAs x 128 threads. CTA owns hidden units j0..j0+3.
// Warp w = gate w. Lane (rg = lane>>3, kg = lane&7):
//   holds W[gate w][unit j0+rg][k = kg*64 .. kg*64+63] in 32 u64 regs.
// h staged to smem each step; dot reads swizzled ((i+kg)&15) -> conflict-free.
// Cross-kg reduction: 3-round shfl_xor. c state in registers (2 cells/thread).
// =====================================================================
#define SCAN_CTAS    128
#define SCAN_THREADS 128
#define SH_FLOATS    (B_ * H_)           // 32768 floats = 128 KB
#define SG_STRIDE    17
#define SG_FLOATS    (B_ * SG_STRIDE)
#define SMEM_BYTES   ((SH_FLOATS + SG_FLOATS) * 4)

__global__ __launch_bounds__(SCAN_THREADS, 1)
void lstm_scan(const float* __restrict__ h0, const float* __restrict__ c0,
               const float* __restrict__ w_hi, const float* __restrict__ w_hf,
               const float* __restrict__ w_hg, const float* __restrict__ w_ho,
               float* __restrict__ out)
{
    extern __shared__ float sm[];
    float* sH = sm;                   // [64][512]
    float* sG = sm + SH_FLOATS;       // [64][17] (16 gate rows + pad)

    const int tid  = threadIdx.x;
    const int w    = tid >> 5;        // warp index == gate index (i,f,g,o)
    const int lane = tid & 31;
    const int rg   = lane >> 3;       // local unit 0..3
    const int kg   = lane & 7;        // k-chunk 0..7 (64 k each)
    const int cta  = blockIdx.x;
    const int j0   = cta * 4;

    // ---- load this lane's weight slice into registers (stays for whole scan)
    const float* wptr = (w == 0) ? w_hi : (w == 1) ? w_hf : (w == 2) ? w_hg : w_ho;
    const u64* ws = (const u64*)(wptr + (size_t)(j0 + rg) * H_ + kg * 64);
    u64 wreg[32];
#pragma unroll
    for (int p = 0; p < 32; p++) wreg[p] = ws[p];

    // elementwise cell mapping: cells tid and tid+128 (b = c>>2, jl = c&3)
    const int b0c = tid >> 2;
    const int b1c = (tid + 128) >> 2;
    const int jl  = tid & 3;
    float creg0 = c0[b0c * H_ + j0 + jl];
    float creg1 = c0[b1c * H_ + j0 + jl];

    const int sgrow = w * 4 + rg;
    const size_t OFS = (size_t)B_ * S_ * H_;

    for (int t = 0; t < S_; t++) {
        const float4* hsrc = (t == 0) ? (const float4*)h0
                                      : (const float4*)g_hbuf[(t - 1) & 1];
        // prefetch x_proj (independent of h; hides DRAM latency behind staging+dot)
        const float* xr0 = g_xproj + ((size_t)t * B_ + b0c) * G4H + (j0 + jl);
        const float* xr1 = g_xproj + ((size_t)t * B_ + b1c) * G4H + (j0 + jl);
        float xi0 = xr0[0], xf0 = xr0[512], xg0 = xr0[1024], xo0 = xr0[1536];
        float xi1 = xr1[0], xf1 = xr1[512], xg1 = xr1[1024], xo1 = xr1[1536];

        // ---- stage h(t-1) into shared (L2-coherent reads)
#pragma unroll 8
        for (int i = 0; i < 64; i++) {
            int idx = tid + i * SCAN_THREADS;   // 0..8191 float4
            ((float4*)sH)[idx] = __ldcg(&hsrc[idx]);
        }
        __syncthreads();

        // ---- dot phase: 2 batches per iteration, 4 f32x2 accumulator chains
        for (int b = 0; b < B_; b += 2) {
            const ulonglong2* p0 = (const ulonglong2*)(sH + (b    ) * H_ + kg * 64);
            const ulonglong2* p1 = (const ulonglong2*)(sH + (b + 1) * H_ + kg * 64);
            u64 a0 = 0ull, a1 = 0ull, a2 = 0ull, a3 = 0ull;
#pragma unroll
            for (int i = 0; i < 16; i += 2) {
                int ia = (i + kg) & 15;
                int ib = (i + 1 + kg) & 15;
                ulonglong2 h0v = p0[ia];
                ulonglong2 h1v = p1[ia];
                ffma2(a0, h0v.x, wreg[2 * ia]); ffma2(a0, h0v.y, wreg[2 * ia + 1]);
                ffma2(a2, h1v.x, wreg[2 * ia]); ffma2(a2, h1v.y, wreg[2 * ia + 1]);
                ulonglong2 h0w = p0[ib];
                ulonglong2 h1w = p1[ib];
                ffma2(a1, h0w.x, wreg[2 * ib]); ffma2(a1, h0w.y, wreg[2 * ib + 1]);
                ffma2(a3, h1w.x, wreg[2 * ib]); ffma2(a3, h1w.y, wreg[2 * ib + 1]);
            }
            float x, y, s0, s1;
            upk2(a0, x, y); s0 = x + y;
            upk2(a1, x, y); s0 += x + y;
            upk2(a2, x, y); s1 = x + y;
            upk2(a3, x, y); s1 += x + y;
            s0 += __shfl_xor_sync(0xffffffffu, s0, 1);
            s0 += __shfl_xor_sync(0xffffffffu, s0, 2);
            s0 += __shfl_xor_sync(0xffffffffu, s0, 4);
            s1 += __shfl_xor_sync(0xffffffffu, s1, 1);
            s1 += __shfl_xor_sync(0xffffffffu, s1, 2);
            s1 += __shfl_xor_sync(0xffffffffu, s1, 4);
            if (kg == 0) {
                sG[b * SG_STRIDE + sgrow]       = s0;
                sG[(b + 1) * SG_STRIDE + sgrow] = s1;
            }
        }
        __syncthreads();

        // ---- elementwise LSTM cell update (2 cells per thread)
        {
            float gi = sG[b0c * SG_STRIDE + jl]      + xi0;
            float gf = sG[b0c * SG_STRIDE + 4 + jl]  + xf0;
            float gg = sG[b0c * SG_STRIDE + 8 + jl]  + xg0;
            float go = sG[b0c * SG_STRIDE + 12 + jl] + xo0;
            float it = fsig_(gi), ft = fsig_(gf), gt = ftanh_(gg), ot = fsig_(go);
            creg0 = ft * creg0 + it * gt;
            float hv = ot * ftanh_(creg0);
            g_hbuf[t & 1][b0c * H_ + j0 + jl] = hv;
            out[((size_t)b0c * S_ + t) * H_ + j0 + jl] = hv;
            if (t == S_ - 1) {
                out[OFS + b0c * H_ + j0 + jl]           = hv;
                out[OFS + B_ * H_ + b0c * H_ + j0 + jl] = creg0;
            }
        }
        {
            float gi = sG[b1c * SG_STRIDE + jl]      + xi1;
            float gf = sG[b1c * SG_STRIDE + 4 + jl]  + xf1;
            float gg = sG[b1c * SG_STRIDE + 8 + jl]  + xg1;
            float go = sG[b1c * SG_STRIDE + 12 + jl] + xo1;
            float it = fsig_(gi), ft = fsig_(gf), gt = ftanh_(gg), ot = fsig_(go);
            creg1 = ft * creg1 + it * gt;
            float hv = ot * ftanh_(creg1);
            g_hbuf[t & 1][b1c * H_ + j0 + jl] = hv;
            out[((size_t)b1c * S_ + t) * H_ + j0 + jl] = hv;
            if (t == S_ - 1) {
                out[OFS + b1c * H_ + j0 + jl]           = hv;
                out[OFS + B_ * H_ + b1c * H_ + j0 + jl] = creg1;
            }
        }

        // ---- grid barrier
        __syncthreads();
        if (tid == 0) {
            __threadfence();
            atomicAdd(&g_count, 1u);
            unsigned target = (unsigned)(t + 1) * (unsigned)SCAN_CTAS;
            while (*(volatile unsigned*)&g_count < target) { }
            __threadfence();
        }
        __syncthreads();
    }
}

// =====================================================================
extern "C" void kernel_launch(void* const* d_in, const int* in_sizes, int n_in,
                              void* d_out, int out_size)
{
    const float* inputs = (const float*)d_in[0];
    const float* h0     = (const float*)d_in[1];
    const float* c0     = (const float*)d_in[2];
    const float* w_ii   = (const float*)d_in[3];
    const float* w_if   = (const float*)d_in[4];
    const float* w_ig   = (const float*)d_in[5];
    const float* w_io   = (const float*)d_in[6];
    const float* w_hi   = (const float*)d_in[7];
    const float* w_hf   = (const float*)d_in[8];
    const float* w_hg   = (const float*)d_in[9];
    const float* w_ho   = (const float*)d_in[10];
    const float* b_ii   = (const float*)d_in[11];
    const float* b_if   = (const float*)d_in[12];
    const float* b_ig   = (const float*)d_in[13];
    const float* b_io   = (const float*)d_in[14];
    const float* b_hi   = (const float*)d_in[15];
    const float* b_hf   = (const float*)d_in[16];
    const float* b_ho   = (const float*)d_in[17];  // dict order: b_ho before b_hg
    const float* b_hg   = (const float*)d_in[18];
    float* out = (float*)d_out;

    cudaFuncSetAttribute(lstm_scan, cudaFuncAttributeMaxDynamicSharedMemorySize, SMEM_BYTES);

    prep_kernel<<<4, 512>>>(b_ii, b_if, b_ig, b_io, b_hi, b_hf, b_hg, b_ho);
    xproj_gemm<<<dim3(G4H / GN, M_TOT / GM), 256>>>(inputs, w_ii, w_if, w_ig, w_io);
    lstm_scan<<<SCAN_CTAS, SCAN_THREADS, SMEM_BYTES>>>(h0, c0, w_hi, w_hf, w_hg, w_ho, out);
}

// round 4
// speedup vs baseline: 1.1656x; 1.1655x over previous
#include <cuda_runtime.h>
#include <cstdint>
#include <cstddef>

// Problem dims
#define B_    64
#define S_    1024
#define I_    512
#define H_    512
#define G4H   2048
#define M_TOT (B_ * S_)        // 65536

typedef unsigned long long u64;

// ---------------- device scratch (no allocations allowed) ----------------
__device__ float    g_xproj[(size_t)S_ * B_ * G4H];   // 512 MB, layout (S, B, 4H)
__device__ float    g_hbuf[2][B_ * H_];               // ping-pong h
__device__ float    g_bias[G4H];
__device__ unsigned g_count;                          // grid barrier counter

// ---------------- f32x2 helpers (Blackwell packed fp32) ----------------
__device__ __forceinline__ u64 pk2(float x, float y) {
    u64 r; asm("mov.b64 %0,{%1,%2};" : "=l"(r) : "f"(x), "f"(y)); return r;
}
__device__ __forceinline__ void upk2(u64 p, float& x, float& y) {
    asm("mov.b64 {%0,%1},%2;" : "=f"(x), "=f"(y) : "l"(p));
}
__device__ __forceinline__ void ffma2(u64& d, u64 a, u64 b) {
    asm("fma.rn.f32x2 %0,%1,%2,%0;" : "+l"(d) : "l"(a), "l"(b));
}

// fast transcendentals (~1e-7 rel err: ex2.approx + rcp.approx)
__device__ __forceinline__ float fexp_(float x) {
    float r; asm("ex2.approx.f32 %0,%1;" : "=f"(r) : "f"(x * 1.4426950408889634f)); return r;
}
__device__ __forceinline__ float frcp_(float x) {
    float r; asm("rcp.approx.f32 %0,%1;" : "=f"(r) : "f"(x)); return r;
}
__device__ __forceinline__ float fsig_(float x)  { return frcp_(1.0f + fexp_(-x)); }
__device__ __forceinline__ float ftanh_(float x) { return 1.0f - 2.0f * frcp_(1.0f + fexp_(2.0f * x)); }

// =====================================================================
// prep: combined bias + barrier counter reset
// =====================================================================
__global__ void prep_kernel(const float* __restrict__ b_ii, const float* __restrict__ b_if,
                            const float* __restrict__ b_ig, const float* __restrict__ b_io,
                            const float* __restrict__ b_hi, const float* __restrict__ b_hf,
                            const float* __restrict__ b_hg, const float* __restrict__ b_ho)
{
    int gidx = blockIdx.x * blockDim.x + threadIdx.x;
    if (gidx == 0) g_count = 0u;
    if (gidx < G4H) {
        int j   = gidx & (H_ - 1);
        int sel = gidx >> 9;
        float v;
        if      (sel == 0) v = b_ii[j] + b_hi[j];
        else if (sel == 1) v = b_if[j] + b_hf[j];
        else if (sel == 2) v = b_ig[j] + b_hg[j];
        else               v = b_io[j] + b_ho[j];
        g_bias[gidx] = v;
    }
}

// =====================================================================
// x_proj GEMM with f32x2 inner loop (unchanged from R2 — no spills there).
// =====================================================================
#define GM 128
#define GN 128
#define GK 16

__global__ __launch_bounds__(256, 2)
void xproj_gemm(const float* __restrict__ A,
                const float* __restrict__ w_ii, const float* __restrict__ w_if,
                const float* __restrict__ w_ig, const float* __restrict__ w_io)
{
    __shared__ float sA[GK][GM + 4];
    __shared__ float sB[GK][GN + 4];

    const int tid   = threadIdx.x;
    const int mBase = blockIdx.y * GM;
    const int nBase = blockIdx.x * GN;
    const float* W = (nBase < 512) ? w_ii : (nBase < 1024) ? w_if : (nBase < 1536) ? w_ig : w_io;
    const int jBase = nBase & (H_ - 1);

    const int lrow = tid >> 1;
    const int lk   = (tid & 1) << 3;
    const float* Ar = A + (size_t)(mBase + lrow) * I_ + lk;
    const float* Br = W + (size_t)(jBase + lrow) * I_ + lk;

    const int tx = tid & 15;
    const int ty = tid >> 4;

    u64 acc2[8][4];
#pragma unroll
    for (int i = 0; i < 8; i++)
#pragma unroll
        for (int j = 0; j < 4; j++) acc2[i][j] = 0ull;

    float4 a0 = *(const float4*)(Ar);
    float4 a1 = *(const float4*)(Ar + 4);
    float4 b0 = *(const float4*)(Br);
    float4 b1 = *(const float4*)(Br + 4);

    for (int k0 = 0; k0 < I_; k0 += GK) {
        sA[lk + 0][lrow] = a0.x; sA[lk + 1][lrow] = a0.y;
        sA[lk + 2][lrow] = a0.z; sA[lk + 3][lrow] = a0.w;
        sA[lk + 4][lrow] = a1.x; sA[lk + 5][lrow] = a1.y;
        sA[lk + 6][lrow] = a1.z; sA[lk + 7][lrow] = a1.w;
        sB[lk + 0][lrow] = b0.x; sB[lk + 1][lrow] = b0.y;
        sB[lk + 2][lrow] = b0.z; sB[lk + 3][lrow] = b0.w;
        sB[lk + 4][lrow] = b1.x; sB[lk + 5][lrow] = b1.y;
        sB[lk + 6][lrow] = b1.z; sB[lk + 7][lrow] = b1.w;
        __syncthreads();

        if (k0 + GK < I_) {
            a0 = *(const float4*)(Ar + k0 + GK);
            a1 = *(const float4*)(Ar + k0 + GK + 4);
            b0 = *(const float4*)(Br + k0 + GK);
            b1 = *(const float4*)(Br + k0 + GK + 4);
        }

#pragma unroll
        for (int kk = 0; kk < GK; kk++) {
            float ar[8];
            *(float4*)(ar)     = *(const float4*)(&sA[kk][ty * 4]);
            *(float4*)(ar + 4) = *(const float4*)(&sA[kk][64 + ty * 4]);
            ulonglong2 bq0 = *(const ulonglong2*)(&sB[kk][tx * 4]);
            ulonglong2 bq1 = *(const ulonglong2*)(&sB[kk][64 + tx * 4]);
#pragma unroll
            for (int i = 0; i < 8; i++) {
                u64 ad = pk2(ar[i], ar[i]);
                ffma2(acc2[i][0], ad, bq0.x);
                ffma2(acc2[i][1], ad, bq0.y);
                ffma2(acc2[i][2], ad, bq1.x);
                ffma2(acc2[i][3], ad, bq1.y);
            }
        }
        __syncthreads();
    }

    float4 bias0 = *(const float4*)(g_bias + nBase + tx * 4);
    float4 bias1 = *(const float4*)(g_bias + nBase + 64 + tx * 4);
#pragma unroll
    for (int i = 0; i < 8; i++) {
        int ml = (i < 4) ? (ty * 4 + i) : (64 + ty * 4 + (i - 4));
        int m  = mBase + ml;
        int b  = m >> 10;
        int t  = m & (S_ - 1);
        float* dst = g_xproj + ((size_t)t * B_ + b) * G4H + nBase;
        float4 v0, v1;
        upk2(acc2[i][0], v0.x, v0.y);
        upk2(acc2[i][1], v0.z, v0.w);
        upk2(acc2[i][2], v1.x, v1.y);
        upk2(acc2[i][3], v1.z, v1.w);
        v0.x += bias0.x; v0.y += bias0.y; v0.z += bias0.z; v0.w += bias0.w;
        v1.x += bias1.x; v1.y += bias1.y; v1.z += bias1.z; v1.w += bias1.w;
        *(float4*)(dst + tx * 4)      = v0;
        *(float4*)(dst + 64 + tx * 4) = v1;
    }
}

// =====================================================================
// Persistent LSTM scan v3: weights in registers (STATIC indexing),
// storage-side XOR swizzle for conflict-free h reads, 256 threads.
//
// 128 CTAs x 256 threads. CTA owns hidden units j0..j0+3 (all 4 gates).
// Warp w (0..7): gate g = w&3, batch-half bh = w>>2 (32 batches).
// Lane (rg = lane>>3, kg = lane&7): unit j0+rg, k-chunk kg (64 k values)
//   -> W slice in wreg[32] u64, indexed ONLY by compile-time constants.
// h stored swizzled: float4 block bk -> bk ^ ((bk>>4)&7). Lane kg reads
// logical block kg*16+i at physical kg*16 + (i^kg): low 3 addr bits = i^kg,
// distinct across kg -> conflict-free; 4 rg-lanes broadcast.
// =====================================================================
#define SCAN_CTAS    128
#define SCAN_THREADS 256
#define SH_FLOATS    (B_ * H_)           // 128 KB
#define SG_STRIDE    17
#define SG_FLOATS    (B_ * SG_STRIDE)
#define SMEM_BYTES   ((SH_FLOATS + SG_FLOATS) * 4)

__global__ __launch_bounds__(SCAN_THREADS, 1)
void lstm_scan(const float* __restrict__ h0, const float* __restrict__ c0,
               const float* __restrict__ w_hi, const float* __restrict__ w_hf,
               const float* __restrict__ w_hg, const float* __restrict__ w_ho,
               float* __restrict__ out)
{
    extern __shared__ float sm[];
    float* sH = sm;                   // [64][512], swizzled float4 blocks
    float* sG = sm + SH_FLOATS;       // [64][17]

    const int tid  = threadIdx.x;
    const int w    = tid >> 5;
    const int g    = w & 3;           // gate
    const int bh   = w >> 2;          // batch half (0 or 1)
    const int lane = tid & 31;
    const int rg   = lane >> 3;       // local unit 0..3
    const int kg   = lane & 7;        // k-chunk 0..7
    const int cta  = blockIdx.x;
    const int j0   = cta * 4;

    // ---- load this lane's weight slice into registers (static indexing only)
    const float* wptr = (g == 0) ? w_hi : (g == 1) ? w_hf : (g == 2) ? w_hg : w_ho;
    const u64* ws = (const u64*)(wptr + (size_t)(j0 + rg) * H_ + kg * 64);
    u64 wreg[32];
#pragma unroll
    for (int p = 0; p < 32; p++) wreg[p] = ws[p];

    // elementwise mapping: 1 cell per thread
    const int eb = tid >> 2;          // batch 0..63
    const int jl = tid & 3;
    float creg = c0[eb * H_ + j0 + jl];

    const int sgrow = g * 4 + rg;
    const int bBase = bh * 32;
    const size_t OFS = (size_t)B_ * S_ * H_;

    ulonglong2* sHu = (ulonglong2*)sH;

    for (int t = 0; t < S_; t++) {
        const float4* hsrc = (t == 0) ? (const float4*)h0
                                      : (const float4*)g_hbuf[(t - 1) & 1];
        // prefetch x_proj (DRAM, independent of h)
        const float* xr = g_xproj + ((size_t)t * B_ + eb) * G4H + (j0 + jl);
        float xi = xr[0], xf = xr[512], xg = xr[1024], xo = xr[1536];

        // ---- stage h(t-1) into shared with XOR-swizzled storage
#pragma unroll 8
        for (int i = 0; i < 32; i++) {
            int idx  = tid + i * SCAN_THREADS;   // float4 index 0..8191
            int b    = idx >> 7;
            int bk   = idx & 127;
            int phys = bk ^ ((bk >> 4) & 7);
            float4 v = __ldcg(&hsrc[idx]);
            ((float4*)sH)[(b << 7) + phys] = v;
        }
        __syncthreads();

        // ---- dot phase: this warp covers 32 batches, 2 per iteration
        for (int bp = 0; bp < 16; bp++) {
            const int b = bBase + bp * 2;
            const ulonglong2* p0 = sHu + ((b    ) << 7) + (kg << 4);
            const ulonglong2* p1 = sHu + ((b + 1) << 7) + (kg << 4);
            u64 a0 = 0ull, a1 = 0ull, a2 = 0ull, a3 = 0ull;
#pragma unroll
            for (int i = 0; i < 16; i += 2) {
                const int o0 = i ^ kg;
                const int o1 = (i + 1) ^ kg;
                ulonglong2 x0 = p0[o0];
                ulonglong2 y0 = p1[o0];
                ffma2(a0, x0.x, wreg[2 * i]);     ffma2(a0, x0.y, wreg[2 * i + 1]);
                ffma2(a2, y0.x, wreg[2 * i]);     ffma2(a2, y0.y, wreg[2 * i + 1]);
                ulonglong2 x1 = p0[o1];
                ulonglong2 y1 = p1[o1];
                ffma2(a1, x1.x, wreg[2 * i + 2]); ffma2(a1, x1.y, wreg[2 * i + 3]);
                ffma2(a3, y1.x, wreg[2 * i + 2]); ffma2(a3, y1.y, wreg[2 * i + 3]);
            }
            float x, y, s0, s1;
            upk2(a0, x, y); s0 = x + y;
            upk2(a1, x, y); s0 += x + y;
            upk2(a2, x, y); s1 = x + y;
            upk2(a3, x, y); s1 += x + y;
            s0 += __shfl_xor_sync(0xffffffffu, s0, 1);
            s0 += __shfl_xor_sync(0xffffffffu, s0, 2);
            s0 += __shfl_xor_sync(0xffffffffu, s0, 4);
            s1 += __shfl_xor_sync(0xffffffffu, s1, 1);
            s1 += __shfl_xor_sync(0xffffffffu, s1, 2);
            s1 += __shfl_xor_sync(0xffffffffu, s1, 4);
            if (kg == 0) {
                sG[b * SG_STRIDE + sgrow]       = s0;
                sG[(b + 1) * SG_STRIDE + sgrow] = s1;
            }
        }
        __syncthreads();

        // ---- elementwise LSTM cell update (1 cell per thread)
        {
            float gi = sG[eb * SG_STRIDE + jl]      + xi;
            float gf = sG[eb * SG_STRIDE + 4 + jl]  + xf;
            float gg = sG[eb * SG_STRIDE + 8 + jl]  + xg;
            float go = sG[eb * SG_STRIDE + 12 + jl] + xo;
            float it = fsig_(gi), ft = fsig_(gf), gt = ftanh_(gg), ot = fsig_(go);
            creg = ft * creg + it * gt;
            float hv = ot * ftanh_(creg);
            g_hbuf[t & 1][eb * H_ + j0 + jl] = hv;
            out[((size_t)eb * S_ + t) * H_ + j0 + jl] = hv;
            if (t == S_ - 1) {
                out[OFS + eb * H_ + j0 + jl]           = hv;
                out[OFS + B_ * H_ + eb * H_ + j0 + jl] = creg;
            }
        }

        // ---- grid barrier (monotone counter)
        __syncthreads();
        if (tid == 0) {
            __threadfence();
            atomicAdd(&g_count, 1u);
            unsigned target = (unsigned)(t + 1) * (unsigned)SCAN_CTAS;
            while (*(volatile unsigned*)&g_count < target) { }
            __threadfence();
        }
        __syncthreads();
    }
}

// =====================================================================
extern "C" void kernel_launch(void* const* d_in, const int* in_sizes, int n_in,
                              void* d_out, int out_size)
{
    const float* inputs = (const float*)d_in[0];
    const float* h0     = (const float*)d_in[1];
    const float* c0     = (const float*)d_in[2];
    const float* w_ii   = (const float*)d_in[3];
    const float* w_if   = (const float*)d_in[4];
    const float* w_ig   = (const float*)d_in[5];
    const float* w_io   = (const float*)d_in[6];
    const float* w_hi   = (const float*)d_in[7];
    const float* w_hf   = (const float*)d_in[8];
    const float* w_hg   = (const float*)d_in[9];
    const float* w_ho   = (const float*)d_in[10];
    const float* b_ii   = (const float*)d_in[11];
    const float* b_if   = (const float*)d_in[12];
    const float* b_ig   = (const float*)d_in[13];
    const float* b_io   = (const float*)d_in[14];
    const float* b_hi   = (const float*)d_in[15];
    const float* b_hf   = (const float*)d_in[16];
    const float* b_ho   = (const float*)d_in[17];  // dict order: b_ho before b_hg
    const float* b_hg   = (const float*)d_in[18];
    float* out = (float*)d_out;

    cudaFuncSetAttribute(lstm_scan, cudaFuncAttributeMaxDynamicSharedMemorySize, SMEM_BYTES);

    prep_kernel<<<4, 512>>>(b_ii, b_if, b_ig, b_io, b_hi, b_hf, b_hg, b_ho);
    xproj_gemm<<<dim3(G4H / GN, M_TOT / GM), 256>>>(inputs, w_ii, w_if, w_ig, w_io);
    lstm_scan<<<SCAN_CTAS, SCAN_THREADS, SMEM_BYTES>>>(h0, c0, w_hi, w_hf, w_hg, w_ho, out);
}

// round 5
// speedup vs baseline: 1.1673x; 1.0014x over previous
#include <cuda_runtime.h>
#include <cstdint>
#include <cstddef>

// Problem dims
#define B_    64
#define S_    1024
#define I_    512
#define H_    512
#define G4H   2048
#define M_TOT (B_ * S_)        // 65536

typedef unsigned long long u64;

// ---------------- device scratch (no allocations allowed) ----------------
__device__ float    g_xproj[(size_t)S_ * B_ * G4H];   // 512 MB, layout (S, B, 4H)
__device__ float    g_hbuf[2][B_ * H_];               // ping-pong h
__device__ float    g_bias[G4H];
__device__ unsigned g_count;                          // grid barrier counter

// ---------------- f32x2 helpers (Blackwell packed fp32) ----------------
__device__ __forceinline__ u64 pk2(float x, float y) {
    u64 r; asm("mov.b64 %0,{%1,%2};" : "=l"(r) : "f"(x), "f"(y)); return r;
}
__device__ __forceinline__ void upk2(u64 p, float& x, float& y) {
    asm("mov.b64 {%0,%1},%2;" : "=f"(x), "=f"(y) : "l"(p));
}
__device__ __forceinline__ void ffma2(u64& d, u64 a, u64 b) {
    asm("fma.rn.f32x2 %0,%1,%2,%0;" : "+l"(d) : "l"(a), "l"(b));
}

// fast transcendentals (~1e-7 rel err: ex2.approx + rcp.approx)
__device__ __forceinline__ float fexp_(float x) {
    float r; asm("ex2.approx.f32 %0,%1;" : "=f"(r) : "f"(x * 1.4426950408889634f)); return r;
}
__device__ __forceinline__ float frcp_(float x) {
    float r; asm("rcp.approx.f32 %0,%1;" : "=f"(r) : "f"(x)); return r;
}
__device__ __forceinline__ float fsig_(float x)  { return frcp_(1.0f + fexp_(-x)); }
__device__ __forceinline__ float ftanh_(float x) { return 1.0f - 2.0f * frcp_(1.0f + fexp_(2.0f * x)); }

// =====================================================================
// prep: combined bias + barrier counter reset
// =====================================================================
__global__ void prep_kernel(const float* __restrict__ b_ii, const float* __restrict__ b_if,
                            const float* __restrict__ b_ig, const float* __restrict__ b_io,
                            const float* __restrict__ b_hi, const float* __restrict__ b_hf,
                            const float* __restrict__ b_hg, const float* __restrict__ b_ho)
{
    int gidx = blockIdx.x * blockDim.x + threadIdx.x;
    if (gidx == 0) g_count = 0u;
    if (gidx < G4H) {
        int j   = gidx & (H_ - 1);
        int sel = gidx >> 9;
        float v;
        if      (sel == 0) v = b_ii[j] + b_hi[j];
        else if (sel == 1) v = b_if[j] + b_hf[j];
        else if (sel == 2) v = b_ig[j] + b_hg[j];
        else               v = b_io[j] + b_ho[j];
        g_bias[gidx] = v;
    }
}

// =====================================================================
// x_proj GEMM with f32x2 inner loop (unchanged from R2 — no spills there).
// =====================================================================
#define GM 128
#define GN 128
#define GK 16

__global__ __launch_bounds__(256, 2)
void xproj_gemm(const float* __restrict__ A,
                const float* __restrict__ w_ii, const float* __restrict__ w_if,
                const float* __restrict__ w_ig, const float* __restrict__ w_io)
{
    __shared__ float sA[GK][GM + 4];
    __shared__ float sB[GK][GN + 4];

    const int tid   = threadIdx.x;
    const int mBase = blockIdx.y * GM;
    const int nBase = blockIdx.x * GN;
    const float* W = (nBase < 512) ? w_ii : (nBase < 1024) ? w_if : (nBase < 1536) ? w_ig : w_io;
    const int jBase = nBase & (H_ - 1);

    const int lrow = tid >> 1;
    const int lk   = (tid & 1) << 3;
    const float* Ar = A + (size_t)(mBase + lrow) * I_ + lk;
    const float* Br = W + (size_t)(jBase + lrow) * I_ + lk;

    const int tx = tid & 15;
    const int ty = tid >> 4;

    u64 acc2[8][4];
#pragma unroll
    for (int i = 0; i < 8; i++)
#pragma unroll
        for (int j = 0; j < 4; j++) acc2[i][j] = 0ull;

    float4 a0 = *(const float4*)(Ar);
    float4 a1 = *(const float4*)(Ar + 4);
    float4 b0 = *(const float4*)(Br);
    float4 b1 = *(const float4*)(Br + 4);

    for (int k0 = 0; k0 < I_; k0 += GK) {
        sA[lk + 0][lrow] = a0.x; sA[lk + 1][lrow] = a0.y;
        sA[lk + 2][lrow] = a0.z; sA[lk + 3][lrow] = a0.w;
        sA[lk + 4][lrow] = a1.x; sA[lk + 5][lrow] = a1.y;
        sA[lk + 6][lrow] = a1.z; sA[lk + 7][lrow] = a1.w;
        sB[lk + 0][lrow] = b0.x; sB[lk + 1][lrow] = b0.y;
        sB[lk + 2][lrow] = b0.z; sB[lk + 3][lrow] = b0.w;
        sB[lk + 4][lrow] = b1.x; sB[lk + 5][lrow] = b1.y;
        sB[lk + 6][lrow] = b1.z; sB[lk + 7][lrow] = b1.w;
        __syncthreads();

        if (k0 + GK < I_) {
            a0 = *(const float4*)(Ar + k0 + GK);
            a1 = *(const float4*)(Ar + k0 + GK + 4);
            b0 = *(const float4*)(Br + k0 + GK);
            b1 = *(const float4*)(Br + k0 + GK + 4);
        }

#pragma unroll
        for (int kk = 0; kk < GK; kk++) {
            float ar[8];
            *(float4*)(ar)     = *(const float4*)(&sA[kk][ty * 4]);
            *(float4*)(ar + 4) = *(const float4*)(&sA[kk][64 + ty * 4]);
            ulonglong2 bq0 = *(const ulonglong2*)(&sB[kk][tx * 4]);
            ulonglong2 bq1 = *(const ulonglong2*)(&sB[kk][64 + tx * 4]);
#pragma unroll
            for (int i = 0; i < 8; i++) {
                u64 ad = pk2(ar[i], ar[i]);
                ffma2(acc2[i][0], ad, bq0.x);
                ffma2(acc2[i][1], ad, bq0.y);
                ffma2(acc2[i][2], ad, bq1.x);
                ffma2(acc2[i][3], ad, bq1.y);
            }
        }
        __syncthreads();
    }

    float4 bias0 = *(const float4*)(g_bias + nBase + tx * 4);
    float4 bias1 = *(const float4*)(g_bias + nBase + 64 + tx * 4);
#pragma unroll
    for (int i = 0; i < 8; i++) {
        int ml = (i < 4) ? (ty * 4 + i) : (64 + ty * 4 + (i - 4));
        int m  = mBase + ml;
        int b  = m >> 10;
        int t  = m & (S_ - 1);
        float* dst = g_xproj + ((size_t)t * B_ + b) * G4H + nBase;
        float4 v0, v1;
        upk2(acc2[i][0], v0.x, v0.y);
        upk2(acc2[i][1], v0.z, v0.w);
        upk2(acc2[i][2], v1.x, v1.y);
        upk2(acc2[i][3], v1.z, v1.w);
        v0.x += bias0.x; v0.y += bias0.y; v0.z += bias0.z; v0.w += bias0.w;
        v1.x += bias1.x; v1.y += bias1.y; v1.z += bias1.z; v1.w += bias1.w;
        *(float4*)(dst + tx * 4)      = v0;
        *(float4*)(dst + 64 + tx * 4) = v1;
    }
}

// =====================================================================
// Persistent LSTM scan v3: weights in registers (STATIC indexing),
// storage-side XOR swizzle for conflict-free h reads, 256 threads.
//
// 128 CTAs x 256 threads. CTA owns hidden units j0..j0+3 (all 4 gates).
// Warp w (0..7): gate g = w&3, batch-half bh = w>>2 (32 batches).
// Lane (rg = lane>>3, kg = lane&7): unit j0+rg, k-chunk kg (64 k values)
//   -> W slice in wreg[32] u64, indexed ONLY by compile-time constants.
// h stored swizzled: float4 block bk -> bk ^ ((bk>>4)&7). Lane kg reads
// logical block kg*16+i at physical kg*16 + (i^kg): low 3 addr bits = i^kg,
// distinct across kg -> conflict-free; 4 rg-lanes broadcast.
// =====================================================================
#define SCAN_CTAS    128
#define SCAN_THREADS 256
#define SH_FLOATS    (B_ * H_)           // 128 KB
#define SG_STRIDE    17
#define SG_FLOATS    (B_ * SG_STRIDE)
#define SMEM_BYTES   ((SH_FLOATS + SG_FLOATS) * 4)

__global__ __launch_bounds__(SCAN_THREADS, 1)
void lstm_scan(const float* __restrict__ h0, const float* __restrict__ c0,
               const float* __restrict__ w_hi, const float* __restrict__ w_hf,
               const float* __restrict__ w_hg, const float* __restrict__ w_ho,
               float* __restrict__ out)
{
    extern __shared__ float sm[];
    float* sH = sm;                   // [64][512], swizzled float4 blocks
    float* sG = sm + SH_FLOATS;       // [64][17]

    const int tid  = threadIdx.x;
    const int w    = tid >> 5;
    const int g    = w & 3;           // gate
    const int bh   = w >> 2;          // batch half (0 or 1)
    const int lane = tid & 31;
    const int rg   = lane >> 3;       // local unit 0..3
    const int kg   = lane & 7;        // k-chunk 0..7
    const int cta  = blockIdx.x;
    const int j0   = cta * 4;

    // ---- load this lane's weight slice into registers (static indexing only)
    const float* wptr = (g == 0) ? w_hi : (g == 1) ? w_hf : (g == 2) ? w_hg : w_ho;
    const u64* ws = (const u64*)(wptr + (size_t)(j0 + rg) * H_ + kg * 64);
    u64 wreg[32];
#pragma unroll
    for (int p = 0; p < 32; p++) wreg[p] = ws[p];

    // elementwise mapping: 1 cell per thread
    const int eb = tid >> 2;          // batch 0..63
    const int jl = tid & 3;
    float creg = c0[eb * H_ + j0 + jl];

    const int sgrow = g * 4 + rg;
    const int bBase = bh * 32;
    const size_t OFS = (size_t)B_ * S_ * H_;

    ulonglong2* sHu = (ulonglong2*)sH;

    for (int t = 0; t < S_; t++) {
        const float4* hsrc = (t == 0) ? (const float4*)h0
                                      : (const float4*)g_hbuf[(t - 1) & 1];
        // prefetch x_proj (DRAM, independent of h)
        const float* xr = g_xproj + ((size_t)t * B_ + eb) * G4H + (j0 + jl);
        float xi = xr[0], xf = xr[512], xg = xr[1024], xo = xr[1536];

        // ---- stage h(t-1) into shared with XOR-swizzled storage
#pragma unroll 8
        for (int i = 0; i < 32; i++) {
            int idx  = tid + i * SCAN_THREADS;   // float4 index 0..8191
            int b    = idx >> 7;
            int bk   = idx & 127;
            int phys = bk ^ ((bk >> 4) & 7);
            float4 v = __ldcg(&hsrc[idx]);
            ((float4*)sH)[(b << 7) + phys] = v;
        }
        __syncthreads();

        // ---- dot phase: this warp covers 32 batches, 2 per iteration
        for (int bp = 0; bp < 16; bp++) {
            const int b = bBase + bp * 2;
            const ulonglong2* p0 = sHu + ((b    ) << 7) + (kg << 4);
            const ulonglong2* p1 = sHu + ((b + 1) << 7) + (kg << 4);
            u64 a0 = 0ull, a1 = 0ull, a2 = 0ull, a3 = 0ull;
#pragma unroll
            for (int i = 0; i < 16; i += 2) {
                const int o0 = i ^ kg;
                const int o1 = (i + 1) ^ kg;
                ulonglong2 x0 = p0[o0];
                ulonglong2 y0 = p1[o0];
                ffma2(a0, x0.x, wreg[2 * i]);     ffma2(a0, x0.y, wreg[2 * i + 1]);
                ffma2(a2, y0.x, wreg[2 * i]);     ffma2(a2, y0.y, wreg[2 * i + 1]);
                ulonglong2 x1 = p0[o1];
                ulonglong2 y1 = p1[o1];
                ffma2(a1, x1.x, wreg[2 * i + 2]); ffma2(a1, x1.y, wreg[2 * i + 3]);
                ffma2(a3, y1.x, wreg[2 * i + 2]); ffma2(a3, y1.y, wreg[2 * i + 3]);
            }
            float x, y, s0, s1;
            upk2(a0, x, y); s0 = x + y;
            upk2(a1, x, y); s0 += x + y;
            upk2(a2, x, y); s1 = x + y;
            upk2(a3, x, y); s1 += x + y;
            s0 += __shfl_xor_sync(0xffffffffu, s0, 1);
            s0 += __shfl_xor_sync(0xffffffffu, s0, 2);
            s0 += __shfl_xor_sync(0xffffffffu, s0, 4);
            s1 += __shfl_xor_sync(0xffffffffu, s1, 1);
            s1 += __shfl_xor_sync(0xffffffffu, s1, 2);
            s1 += __shfl_xor_sync(0xffffffffu, s1, 4);
            if (kg == 0) {
                sG[b * SG_STRIDE + sgrow]       = s0;
                sG[(b + 1) * SG_STRIDE + sgrow] = s1;
            }
        }
        __syncthreads();

        // ---- elementwise LSTM cell update (1 cell per thread)
        {
            float gi = sG[eb * SG_STRIDE + jl]      + xi;
            float gf = sG[eb * SG_STRIDE + 4 + jl]  + xf;
            float gg = sG[eb * SG_STRIDE + 8 + jl]  + xg;
            float go = sG[eb * SG_STRIDE + 12 + jl] + xo;
            float it = fsig_(gi), ft = fsig_(gf), gt = ftanh_(gg), ot = fsig_(go);
            creg = ft * creg + it * gt;
            float hv = ot * ftanh_(creg);
            g_hbuf[t & 1][eb * H_ + j0 + jl] = hv;
            out[((size_t)eb * S_ + t) * H_ + j0 + jl] = hv;
            if (t == S_ - 1) {
                out[OFS + eb * H_ + j0 + jl]           = hv;
                out[OFS + B_ * H_ + eb * H_ + j0 + jl] = creg;
            }
        }

        // ---- grid barrier (monotone counter)
        __syncthreads();
        if (tid == 0) {
            __threadfence();
            atomicAdd(&g_count, 1u);
            unsigned target = (unsigned)(t + 1) * (unsigned)SCAN_CTAS;
            while (*(volatile unsigned*)&g_count < target) { }
            __threadfence();
        }
        __syncthreads();
    }
}

// =====================================================================
extern "C" void kernel_launch(void* const* d_in, const int* in_sizes, int n_in,
                              void* d_out, int out_size)
{
    const float* inputs = (const float*)d_in[0];
    const float* h0     = (const float*)d_in[1];
    const float* c0     = (const float*)d_in[2];
    const float* w_ii   = (const float*)d_in[3];
    const float* w_if   = (const float*)d_in[4];
    const float* w_ig   = (const float*)d_in[5];
    const float* w_io   = (const float*)d_in[6];
    const float* w_hi   = (const float*)d_in[7];
    const float* w_hf   = (const float*)d_in[8];
    const float* w_hg   = (const float*)d_in[9];
    const float* w_ho   = (const float*)d_in[10];
    const float* b_ii   = (const float*)d_in[11];
    const float* b_if   = (const float*)d_in[12];
    const float* b_ig   = (const float*)d_in[13];
    const float* b_io   = (const float*)d_in[14];
    const float* b_hi   = (const float*)d_in[15];
    const float* b_hf   = (const float*)d_in[16];
    const float* b_ho   = (const float*)d_in[17];  // dict order: b_ho before b_hg
    const float* b_hg   = (const float*)d_in[18];
    float* out = (float*)d_out;

    cudaFuncSetAttribute(lstm_scan, cudaFuncAttributeMaxDynamicSharedMemorySize, SMEM_BYTES);

    prep_kernel<<<4, 512>>>(b_ii, b_if, b_ig, b_io, b_hi, b_hf, b_hg, b_ho);
    xproj_gemm<<<dim3(G4H / GN, M_TOT / GM), 256>>>(inputs, w_ii, w_if, w_ig, w_io);
    lstm_scan<<<SCAN_CTAS, SCAN_THREADS, SMEM_BYTES>>>(h0, c0, w_hi, w_hf, w_hg, w_ho, out);
}